// round 3
// baseline (speedup 1.0000x reference)
#include <cuda_runtime.h>
#include <math.h>

#define TOKENS 8192
#define DMODEL 768
#define DMLP   3072
#define NH     12
#define DH     64
#define SEQ    1024
#define BATCH  8
#define QKVLD  2304

// ---------------- scratch (device globals: no allocs allowed) ----------------
__device__ float g_x1 [TOKENS*DMODEL];
__device__ float g_wqkv[DMODEL*QKVLD];
__device__ float g_bqkv[QKVLD];
__device__ float g_qkv[TOKENS*QKVLD];
__device__ float g_z  [TOKENS*DMODEL];
__device__ float g_mid[TOKENS*DMODEL];
__device__ float g_x2 [TOKENS*DMODEL];
__device__ float g_h  [TOKENS*DMLP];

__device__ __forceinline__ float fast_tanh(float x){
    float r; asm("tanh.approx.f32 %0, %1;" : "=f"(r) : "f"(x)); return r;
}
__device__ __forceinline__ float gelu_fn(float x){
    float u = x + 0.044715f*x*x*x;
    return 0.5f*x*(1.0f + fast_tanh(0.7978845608028654f*u));
}

// ---------------- repack W_Q/W_K/W_V [12,768,64] -> [768, 2304] ----------------
__global__ void __launch_bounds__(256) repack_kernel(
    const float* __restrict__ WQ, const float* __restrict__ WK, const float* __restrict__ WV,
    const float* __restrict__ bQ, const float* __restrict__ bK, const float* __restrict__ bV)
{
    int idx = blockIdx.x*256 + threadIdx.x;
    if (idx < DMODEL*QKVLD) {
        int d   = idx / QKVLD;
        int col = idx % QKVLD;
        int which = col / DMODEL;
        int r     = col % DMODEL;
        int h = r >> 6, e = r & 63;
        const float* W = (which==0) ? WQ : (which==1) ? WK : WV;
        g_wqkv[idx] = W[(h*DMODEL + d)*DH + e];
    }
    if (idx < QKVLD) {
        int which = idx / DMODEL, r = idx % DMODEL;
        const float* bb = (which==0) ? bQ : (which==1) ? bK : bV;
        g_bqkv[idx] = bb[r];
    }
}

// ---------------- LayerNorm: one block per token ----------------
__global__ void __launch_bounds__(256) ln_kernel(
    const float* __restrict__ x, const float* __restrict__ w,
    const float* __restrict__ b, float* __restrict__ y)
{
    int t = blockIdx.x;
    const float* xr = x + (size_t)t*DMODEL;
    float*       yr = y + (size_t)t*DMODEL;
    int tid = threadIdx.x;
    float v0 = xr[tid], v1 = xr[tid+256], v2 = xr[tid+512];
    float s  = v0+v1+v2;
    float s2 = v0*v0 + v1*v1 + v2*v2;
    #pragma unroll
    for (int o=16;o>0;o>>=1){ s += __shfl_xor_sync(~0u,s,o); s2 += __shfl_xor_sync(~0u,s2,o); }
    __shared__ float sh[16];
    int warp = tid>>5, lane = tid&31;
    if (lane==0){ sh[warp]=s; sh[8+warp]=s2; }
    __syncthreads();
    if (tid==0){
        float a=0.f,c=0.f;
        #pragma unroll
        for (int i=0;i<8;i++){ a+=sh[i]; c+=sh[8+i]; }
        float mean = a*(1.0f/DMODEL);
        float var  = c*(1.0f/DMODEL) - mean*mean;
        sh[0]=mean; sh[1]=rsqrtf(var+1e-5f);
    }
    __syncthreads();
    float mean=sh[0], rstd=sh[1];
    yr[tid]     = (v0-mean)*rstd*w[tid]     + b[tid];
    yr[tid+256] = (v1-mean)*rstd*w[tid+256] + b[tid+256];
    yr[tid+512] = (v2-mean)*rstd*w[tid+512] + b[tid+512];
}

// ---------------- SGEMM 128x128, K-step 8, 8x8 per thread, double-buffered ----
// C[M,N] = A[M,K] @ B[K,N] + bias[N]  (+gelu) (+res[M,N])
template<bool GELU, bool RES>
__global__ void __launch_bounds__(256,2) sgemm128(
    const float* __restrict__ A, const float* __restrict__ B,
    const float* __restrict__ bias, const float* __restrict__ res,
    float* __restrict__ C, int M, int N, int K)
{
    __shared__ __align__(16) float As[2][8][128];
    __shared__ __align__(16) float Bs[2][8][128];

    int tid = threadIdx.x;
    int m0 = blockIdx.y*128, n0 = blockIdx.x*128;
    int tx = tid & 15, ty = tid >> 4;

    int arow = tid >> 1;          // 0..127
    int akc  = (tid & 1) * 4;     // 0 or 4
    int bk   = tid >> 5;          // 0..7
    int bc4  = (tid & 31) * 4;    // 0..124

    const float* Aptr = A + (size_t)(m0+arow)*K + akc;
    const float* Bptr = B + (size_t)bk*N + n0 + bc4;

    float acc[8][8];
    #pragma unroll
    for (int i=0;i<8;i++)
        #pragma unroll
        for (int j=0;j<8;j++) acc[i][j]=0.f;

    // prologue: fill buffer 0 with k0=0
    {
        float4 av = *(const float4*)(Aptr);
        float4 bv = *(const float4*)(Bptr);
        As[0][akc+0][arow]=av.x; As[0][akc+1][arow]=av.y;
        As[0][akc+2][arow]=av.z; As[0][akc+3][arow]=av.w;
        *(float4*)&Bs[0][bk][bc4] = bv;
    }
    __syncthreads();

    int buf = 0;
    for (int k0=8; k0<K; k0+=8){
        // prefetch next tile from global into registers
        float4 av = *(const float4*)(Aptr + k0);
        float4 bv = *(const float4*)(Bptr + (size_t)k0*N);

        // compute on current buffer
        #pragma unroll
        for (int k=0;k<8;k++){
            float4 a0 = *(const float4*)&As[buf][k][ty*4];
            float4 a1 = *(const float4*)&As[buf][k][64+ty*4];
            float4 b0 = *(const float4*)&Bs[buf][k][tx*4];
            float4 b1 = *(const float4*)&Bs[buf][k][64+tx*4];
            float a[8]={a0.x,a0.y,a0.z,a0.w,a1.x,a1.y,a1.z,a1.w};
            float b[8]={b0.x,b0.y,b0.z,b0.w,b1.x,b1.y,b1.z,b1.w};
            #pragma unroll
            for (int i=0;i<8;i++)
                #pragma unroll
                for (int j=0;j<8;j++) acc[i][j] = fmaf(a[i],b[j],acc[i][j]);
        }

        // store prefetched tile into the other buffer
        int nb = buf ^ 1;
        As[nb][akc+0][arow]=av.x; As[nb][akc+1][arow]=av.y;
        As[nb][akc+2][arow]=av.z; As[nb][akc+3][arow]=av.w;
        *(float4*)&Bs[nb][bk][bc4] = bv;
        __syncthreads();
        buf = nb;
    }

    // epilogue compute on final buffer
    #pragma unroll
    for (int k=0;k<8;k++){
        float4 a0 = *(const float4*)&As[buf][k][ty*4];
        float4 a1 = *(const float4*)&As[buf][k][64+ty*4];
        float4 b0 = *(const float4*)&Bs[buf][k][tx*4];
        float4 b1 = *(const float4*)&Bs[buf][k][64+tx*4];
        float a[8]={a0.x,a0.y,a0.z,a0.w,a1.x,a1.y,a1.z,a1.w};
        float b[8]={b0.x,b0.y,b0.z,b0.w,b1.x,b1.y,b1.z,b1.w};
        #pragma unroll
        for (int i=0;i<8;i++)
            #pragma unroll
            for (int j=0;j<8;j++) acc[i][j] = fmaf(a[i],b[j],acc[i][j]);
    }

    #pragma unroll
    for (int i=0;i<8;i++){
        int m = m0 + ((i<4) ? (ty*4+i) : (64 + ty*4 + (i-4)));
        #pragma unroll
        for (int jg=0; jg<2; jg++){
            int n = n0 + jg*64 + tx*4;
            float c0 = acc[i][jg*4+0] + bias[n+0];
            float c1 = acc[i][jg*4+1] + bias[n+1];
            float c2 = acc[i][jg*4+2] + bias[n+2];
            float c3 = acc[i][jg*4+3] + bias[n+3];
            if (GELU){ c0=gelu_fn(c0); c1=gelu_fn(c1); c2=gelu_fn(c2); c3=gelu_fn(c3); }
            size_t off = (size_t)m*N + n;
            if (RES){
                float4 r4 = *(const float4*)(res + off);
                c0+=r4.x; c1+=r4.y; c2+=r4.z; c3+=r4.w;
            }
            float4 v = make_float4(c0,c1,c2,c3);
            *(float4*)(C + off) = v;
        }
    }
}

// ---------------- Flash attention: block per (q-tile64, head, batch) ----------------
__global__ void __launch_bounds__(256) attn_kernel(
    const float* __restrict__ QKV, float* __restrict__ Z)
{
    __shared__ __align__(16) float Qs[64][64];   // [q][d], pre-scaled
    __shared__ __align__(16) float KT[64][64];   // [d][k]  (reused as P[q][k])
    __shared__ __align__(16) float Vs[64][64];   // [k][e]

    int qt = gridDim.x - 1 - blockIdx.x;  // longest blocks launch first
    int h  = blockIdx.y;
    int b  = blockIdx.z;
    int q0 = qt*64;
    int tid = threadIdx.x, tx = tid & 15, ty = tid >> 4;

    const float* base = QKV + (size_t)b*SEQ*QKVLD + h*DH;

    // load Q tile, scaled by 1/sqrt(64)
    #pragma unroll
    for (int i=0;i<4;i++){
        int idx = tid + i*256;           // 0..1023
        int r = idx >> 4, c4 = (idx & 15)*4;
        float4 v = *(const float4*)(base + (size_t)(q0+r)*QKVLD + c4);
        v.x*=0.125f; v.y*=0.125f; v.z*=0.125f; v.w*=0.125f;
        *(float4*)&Qs[r][c4] = v;
    }

    float m[4], l[4], acc[4][4];
    #pragma unroll
    for (int i=0;i<4;i++){
        m[i]=-INFINITY; l[i]=0.f;
        #pragma unroll
        for (int j=0;j<4;j++) acc[i][j]=0.f;
    }

    int nkt = qt + 1;
    for (int kt=0; kt<nkt; kt++){
        int k0 = kt*64;
        __syncthreads();   // prior iter done with KT/Vs
        #pragma unroll
        for (int i=0;i<4;i++){
            int idx = tid + i*256;
            int r = idx >> 4, c4 = (idx & 15)*4;
            float4 kv = *(const float4*)(base + 768  + (size_t)(k0+r)*QKVLD + c4);
            KT[c4+0][r]=kv.x; KT[c4+1][r]=kv.y; KT[c4+2][r]=kv.z; KT[c4+3][r]=kv.w;
            float4 vv = *(const float4*)(base + 1536 + (size_t)(k0+r)*QKVLD + c4);
            *(float4*)&Vs[r][c4] = vv;
        }
        __syncthreads();

        float s[4][4];
        #pragma unroll
        for (int i=0;i<4;i++)
            #pragma unroll
            for (int j=0;j<4;j++) s[i][j]=0.f;

        #pragma unroll
        for (int d=0; d<64; d+=4){
            float4 q4[4], k4[4];
            #pragma unroll
            for (int ii=0;ii<4;ii++) q4[ii] = *(const float4*)&Qs[ty*4+ii][d];
            #pragma unroll
            for (int c=0;c<4;c++)    k4[c]  = *(const float4*)&KT[d+c][tx*4];
            #pragma unroll
            for (int ii=0;ii<4;ii++){
                float qa[4] = {q4[ii].x, q4[ii].y, q4[ii].z, q4[ii].w};
                #pragma unroll
                for (int c=0;c<4;c++){
                    s[ii][0] = fmaf(qa[c], k4[c].x, s[ii][0]);
                    s[ii][1] = fmaf(qa[c], k4[c].y, s[ii][1]);
                    s[ii][2] = fmaf(qa[c], k4[c].z, s[ii][2]);
                    s[ii][3] = fmaf(qa[c], k4[c].w, s[ii][3]);
                }
            }
        }

        if (kt == qt){   // diagonal tile: causal mask
            #pragma unroll
            for (int ii=0;ii<4;ii++)
                #pragma unroll
                for (int jj=0;jj<4;jj++)
                    if (k0 + tx*4 + jj > q0 + ty*4 + ii) s[ii][jj] = -INFINITY;
        }

        // online softmax update
        #pragma unroll
        for (int ii=0;ii<4;ii++){
            float tm = fmaxf(fmaxf(s[ii][0],s[ii][1]), fmaxf(s[ii][2],s[ii][3]));
            #pragma unroll
            for (int o=8;o>0;o>>=1) tm = fmaxf(tm, __shfl_xor_sync(~0u, tm, o));
            float nm = fmaxf(m[ii], tm);
            float alpha = __expf(m[ii]-nm);
            float psum = 0.f;
            #pragma unroll
            for (int jj=0;jj<4;jj++){
                float p = __expf(s[ii][jj]-nm);
                s[ii][jj] = p; psum += p;
            }
            #pragma unroll
            for (int o=8;o>0;o>>=1) psum += __shfl_xor_sync(~0u, psum, o);
            l[ii] = l[ii]*alpha + psum;
            m[ii] = nm;
            #pragma unroll
            for (int jj=0;jj<4;jj++) acc[ii][jj]*=alpha;
        }

        __syncthreads();  // all threads done reading KT (scores)
        #pragma unroll
        for (int ii=0;ii<4;ii++)
            *(float4*)&KT[ty*4+ii][tx*4] = make_float4(s[ii][0],s[ii][1],s[ii][2],s[ii][3]);
        __syncthreads();

        // acc += P @ V
        #pragma unroll
        for (int k=0;k<64;k+=4){
            float4 p4[4], v4[4];
            #pragma unroll
            for (int ii=0;ii<4;ii++) p4[ii] = *(const float4*)&KT[ty*4+ii][k];
            #pragma unroll
            for (int c=0;c<4;c++)    v4[c]  = *(const float4*)&Vs[k+c][tx*4];
            #pragma unroll
            for (int ii=0;ii<4;ii++){
                float pa[4] = {p4[ii].x, p4[ii].y, p4[ii].z, p4[ii].w};
                #pragma unroll
                for (int c=0;c<4;c++){
                    acc[ii][0] = fmaf(pa[c], v4[c].x, acc[ii][0]);
                    acc[ii][1] = fmaf(pa[c], v4[c].y, acc[ii][1]);
                    acc[ii][2] = fmaf(pa[c], v4[c].z, acc[ii][2]);
                    acc[ii][3] = fmaf(pa[c], v4[c].w, acc[ii][3]);
                }
            }
        }
    }

    float* outp = Z + ((size_t)b*SEQ + q0)*DMODEL + h*DH;
    #pragma unroll
    for (int ii=0;ii<4;ii++){
        float inv = 1.0f/l[ii];
        float4 v = make_float4(acc[ii][0]*inv, acc[ii][1]*inv, acc[ii][2]*inv, acc[ii][3]*inv);
        *(float4*)&outp[(size_t)(ty*4+ii)*DMODEL + tx*4] = v;
    }
}

// ---------------- launch ----------------
extern "C" void kernel_launch(void* const* d_in, const int* in_sizes, int n_in,
                              void* d_out, int out_size)
{
    const float* resid = (const float*)d_in[0];
    const float* WQ    = (const float*)d_in[1];
    const float* WK    = (const float*)d_in[2];
    const float* WV    = (const float*)d_in[3];
    const float* WO    = (const float*)d_in[4];   // [12,64,768] == [768,768] row-major
    const float* bQ    = (const float*)d_in[5];
    const float* bK    = (const float*)d_in[6];
    const float* bV    = (const float*)d_in[7];
    const float* bO    = (const float*)d_in[8];
    const float* ln1w  = (const float*)d_in[9];
    const float* ln1b  = (const float*)d_in[10];
    const float* ln2w  = (const float*)d_in[11];
    const float* ln2b  = (const float*)d_in[12];
    const float* Win   = (const float*)d_in[13];
    const float* bin   = (const float*)d_in[14];
    const float* Wout  = (const float*)d_in[15];
    const float* bout  = (const float*)d_in[16];
    float* out = (float*)d_out;

    float *x1, *wqkv, *bqkv, *qkv, *z, *mid, *x2, *hbuf;
    cudaGetSymbolAddress((void**)&x1,   g_x1);
    cudaGetSymbolAddress((void**)&wqkv, g_wqkv);
    cudaGetSymbolAddress((void**)&bqkv, g_bqkv);
    cudaGetSymbolAddress((void**)&qkv,  g_qkv);
    cudaGetSymbolAddress((void**)&z,    g_z);
    cudaGetSymbolAddress((void**)&mid,  g_mid);
    cudaGetSymbolAddress((void**)&x2,   g_x2);
    cudaGetSymbolAddress((void**)&hbuf, g_h);

    repack_kernel<<<(DMODEL*QKVLD + 255)/256, 256>>>(WQ, WK, WV, bQ, bK, bV);
    ln_kernel<<<TOKENS, 256>>>(resid, ln1w, ln1b, x1);
    sgemm128<false,false><<<dim3(QKVLD/128, TOKENS/128), 256>>>(
        x1, wqkv, bqkv, nullptr, qkv, TOKENS, QKVLD, DMODEL);
    attn_kernel<<<dim3(SEQ/64, NH, BATCH), 256>>>(qkv, z);
    sgemm128<false,true><<<dim3(DMODEL/128, TOKENS/128), 256>>>(
        z, WO, bO, resid, mid, TOKENS, DMODEL, DMODEL);
    ln_kernel<<<TOKENS, 256>>>(mid, ln2w, ln2b, x2);
    sgemm128<true,false><<<dim3(DMLP/128, TOKENS/128), 256>>>(
        x2, Win, bin, nullptr, hbuf, TOKENS, DMLP, DMODEL);
    sgemm128<false,true><<<dim3(DMODEL/128, TOKENS/128), 256>>>(
        hbuf, Wout, bout, mid, out, TOKENS, DMODEL, DMLP);
}

// round 12
// speedup vs baseline: 2.5144x; 2.5144x over previous
#include <cuda_runtime.h>
#include <cuda_fp16.h>
#include <math.h>

#define TOKENS 8192
#define DMODEL 768
#define DMLP   3072
#define NH     12
#define DH     64
#define SEQ    1024
#define BATCH  8
#define QKVLD  2304
#define SA     40   // smem row stride in halves (80B): conflict-free for ldmatrix

// ---------------- scratch (device globals: no allocs allowed) ----------------
__device__ __half g_x1h [TOKENS*DMODEL];
__device__ __half g_x2h [TOKENS*DMODEL];
__device__ __half g_zh  [TOKENS*DMODEL];
__device__ __half g_hh  [TOKENS*DMLP];
__device__ __half g_wqkvh[QKVLD*DMODEL];   // [N=2304][K=768]
__device__ __half g_woh  [DMODEL*DMODEL];  // [N=768][K=768]
__device__ __half g_winh [DMLP*DMODEL];    // [N=3072][K=768]
__device__ __half g_wouth[DMODEL*DMLP];    // [N=768][K=3072]
__device__ float  g_bqkv[QKVLD];
__device__ float  g_qkv [TOKENS*QKVLD];
__device__ float  g_mid [TOKENS*DMODEL];

// ---------------- small helpers ----------------
__device__ __forceinline__ float fast_tanh(float x){
    float r; asm("tanh.approx.f32 %0, %1;" : "=f"(r) : "f"(x)); return r;
}
__device__ __forceinline__ float gelu_fn(float x){
    float u = x + 0.044715f*x*x*x;
    return 0.5f*x*(1.0f + fast_tanh(0.7978845608028654f*u));
}
__device__ __forceinline__ unsigned smem_u32(const void* p){
    unsigned a;
    asm("{ .reg .u64 t; cvta.to.shared.u64 t, %1; cvt.u32.u64 %0, t; }" : "=r"(a) : "l"(p));
    return a;
}

#define LDSM4(r0,r1,r2,r3, addr) \
    asm volatile("ldmatrix.sync.aligned.m8n8.x4.shared.b16 {%0,%1,%2,%3}, [%4];" \
        : "=r"(r0),"=r"(r1),"=r"(r2),"=r"(r3) : "r"(addr))

#define MMA16816(c0,c1,c2,c3, a0,a1,a2,a3, b0,b1) \
    asm volatile("mma.sync.aligned.m16n8k16.row.col.f32.f16.f16.f32 " \
        "{%0,%1,%2,%3}, {%4,%5,%6,%7}, {%8,%9}, {%0,%1,%2,%3};" \
        : "+f"(c0),"+f"(c1),"+f"(c2),"+f"(c3) \
        : "r"(a0),"r"(a1),"r"(a2),"r"(a3), "r"(b0),"r"(b1))

// ---------------- weight repack kernels (fp32 -> fp16, transposed to [N][K]) --
__global__ void __launch_bounds__(256) repack_qkv_kernel(
    const float* __restrict__ WQ, const float* __restrict__ WK, const float* __restrict__ WV,
    const float* __restrict__ bQ, const float* __restrict__ bK, const float* __restrict__ bV)
{
    int idx = blockIdx.x*256 + threadIdx.x;
    if (idx < QKVLD*DMODEL) {
        int n = idx / DMODEL;       // output column 0..2303
        int k = idx % DMODEL;       // input dim
        int which = n / DMODEL;
        int r = n % DMODEL;
        int h = r >> 6, e = r & 63;
        const float* W = (which==0) ? WQ : (which==1) ? WK : WV;
        g_wqkvh[idx] = __float2half(W[(h*DMODEL + k)*DH + e]);
    }
    if (idx < QKVLD) {
        int which = idx / DMODEL, r = idx % DMODEL;
        const float* bb = (which==0) ? bQ : (which==1) ? bK : bV;
        g_bqkv[idx] = bb[r];
    }
}

// out[n*K + k] = W[k*N + n]
__global__ void __launch_bounds__(256) repack_t_kernel(
    const float* __restrict__ W, __half* __restrict__ out, int N, int K)
{
    int idx = blockIdx.x*256 + threadIdx.x;
    if (idx < N*K) {
        int n = idx / K, k = idx % K;
        out[idx] = __float2half(W[(size_t)k*N + n]);
    }
}

// ---------------- LayerNorm: one block per token, fp16 out ----------------
__global__ void __launch_bounds__(256) ln_kernel(
    const float* __restrict__ x, const float* __restrict__ w,
    const float* __restrict__ b, __half* __restrict__ y)
{
    int t = blockIdx.x;
    const float* xr = x + (size_t)t*DMODEL;
    __half*      yr = y + (size_t)t*DMODEL;
    int tid = threadIdx.x;
    float v0 = xr[tid], v1 = xr[tid+256], v2 = xr[tid+512];
    float s  = v0+v1+v2;
    float s2 = v0*v0 + v1*v1 + v2*v2;
    #pragma unroll
    for (int o=16;o>0;o>>=1){ s += __shfl_xor_sync(~0u,s,o); s2 += __shfl_xor_sync(~0u,s2,o); }
    __shared__ float sh[16];
    int warp = tid>>5, lane = tid&31;
    if (lane==0){ sh[warp]=s; sh[8+warp]=s2; }
    __syncthreads();
    if (tid==0){
        float a=0.f,c=0.f;
        #pragma unroll
        for (int i=0;i<8;i++){ a+=sh[i]; c+=sh[8+i]; }
        float mean = a*(1.0f/DMODEL);
        float var  = c*(1.0f/DMODEL) - mean*mean;
        sh[0]=mean; sh[1]=rsqrtf(var+1e-5f);
    }
    __syncthreads();
    float mean=sh[0], rstd=sh[1];
    yr[tid]     = __float2half((v0-mean)*rstd*w[tid]     + b[tid]);
    yr[tid+256] = __float2half((v1-mean)*rstd*w[tid+256] + b[tid+256]);
    yr[tid+512] = __float2half((v2-mean)*rstd*w[tid+512] + b[tid+512]);
}

// ---------------- HMMA fp16 GEMM: C[M,Ntot] = A[M,K] @ B[Ntot,K]^T ------------
// CTA tile 128x128, BK=32, 8 warps (2x4), warp tile 64x32 via m16n8k16.
__device__ __forceinline__ void compute_tile(unsigned Abase, unsigned Bbase,
                                             float c[4][4][4])
{
    #pragma unroll
    for (int kk=0; kk<2; kk++){
        unsigned a[4][4], b[2][4];
        #pragma unroll
        for (int mi=0; mi<4; mi++)
            LDSM4(a[mi][0],a[mi][1],a[mi][2],a[mi][3],
                  Abase + (unsigned)((mi*16*SA + kk*16)*2));
        #pragma unroll
        for (int ni=0; ni<2; ni++)
            LDSM4(b[ni][0],b[ni][1],b[ni][2],b[ni][3],
                  Bbase + (unsigned)((ni*16*SA + kk*16)*2));
        #pragma unroll
        for (int mi=0; mi<4; mi++)
            #pragma unroll
            for (int j=0; j<4; j++){
                int ni = j>>1, s = j&1;
                MMA16816(c[mi][j][0],c[mi][j][1],c[mi][j][2],c[mi][j][3],
                         a[mi][0],a[mi][1],a[mi][2],a[mi][3],
                         b[ni][s], b[ni][s+2]);
            }
    }
}

template<bool GELU, bool RES, bool W32, bool W16>
__global__ void __launch_bounds__(256,2) hgemm(
    const __half* __restrict__ A, const __half* __restrict__ Bw,
    const float* __restrict__ bias, const float* __restrict__ res,
    float* __restrict__ C32, __half* __restrict__ C16, int Ntot, int K)
{
    __shared__ __align__(16) __half As[2][128*SA];
    __shared__ __align__(16) __half Bs[2][128*SA];

    int tid = threadIdx.x, lane = tid&31, wid = tid>>5;
    int wm = wid>>2, wn = wid&3;
    int m0 = blockIdx.y*128, n0 = blockIdx.x*128;

    int lr = tid>>1;            // load row 0..127
    int lc = (tid&1)*16;        // half col 0 or 16
    const __half* Ap = A  + (size_t)(m0+lr)*K + lc;
    const __half* Bp = Bw + (size_t)(n0+lr)*K + lc;
    int soff = lr*SA + lc;

    float c[4][4][4];
    #pragma unroll
    for (int i=0;i<4;i++)
        #pragma unroll
        for (int j=0;j<4;j++)
            #pragma unroll
            for (int k=0;k<4;k++) c[i][j][k]=0.f;

    unsigned a_lane = (unsigned)(((wm*64 + (lane&15))*SA + (lane>>4)*8)*2);
    unsigned b_lane = (unsigned)(((wn*32 + (lane&15))*SA + (lane>>4)*8)*2);
    unsigned As0 = smem_u32(&As[0][0]), As1 = smem_u32(&As[1][0]);
    unsigned Bs0 = smem_u32(&Bs[0][0]), Bs1 = smem_u32(&Bs[1][0]);

    // prologue: fill buffer 0
    {
        uint4 a0 = *(const uint4*)(Ap);
        uint4 a1 = *(const uint4*)(Ap+8);
        uint4 b0 = *(const uint4*)(Bp);
        uint4 b1 = *(const uint4*)(Bp+8);
        *(uint4*)&As[0][soff]   = a0; *(uint4*)&As[0][soff+8] = a1;
        *(uint4*)&Bs[0][soff]   = b0; *(uint4*)&Bs[0][soff+8] = b1;
    }
    __syncthreads();

    int nks = K >> 5;
    int buf = 0;
    for (int ks=1; ks<nks; ks++){
        const __half* Ap2 = Ap + ks*32;
        const __half* Bp2 = Bp + ks*32;
        uint4 a0 = *(const uint4*)(Ap2);
        uint4 a1 = *(const uint4*)(Ap2+8);
        uint4 b0 = *(const uint4*)(Bp2);
        uint4 b1 = *(const uint4*)(Bp2+8);

        compute_tile((buf?As1:As0)+a_lane, (buf?Bs1:Bs0)+b_lane, c);

        int nb = buf^1;
        __half* Asw = nb ? &As[1][0] : &As[0][0];
        __half* Bsw = nb ? &Bs[1][0] : &Bs[0][0];
        *(uint4*)&Asw[soff]   = a0; *(uint4*)&Asw[soff+8] = a1;
        *(uint4*)&Bsw[soff]   = b0; *(uint4*)&Bsw[soff+8] = b1;
        __syncthreads();
        buf = nb;
    }
    compute_tile((buf?As1:As0)+a_lane, (buf?Bs1:Bs0)+b_lane, c);

    // epilogue: c-frag (m16n8): c0,c1 at (row=lane>>2, col=2*(lane&3)), c2,c3 at row+8
    int rr = lane>>2, cc = (lane&3)*2;
    #pragma unroll
    for (int mi=0; mi<4; mi++){
        int mrow0 = m0 + wm*64 + mi*16 + rr;
        int mrow1 = mrow0 + 8;
        #pragma unroll
        for (int j=0; j<4; j++){
            int n = n0 + wn*32 + j*8 + cc;
            float2 b2 = *(const float2*)(bias + n);
            float v00 = c[mi][j][0] + b2.x, v01 = c[mi][j][1] + b2.y;
            float v10 = c[mi][j][2] + b2.x, v11 = c[mi][j][3] + b2.y;
            if (GELU){
                v00=gelu_fn(v00); v01=gelu_fn(v01);
                v10=gelu_fn(v10); v11=gelu_fn(v11);
            }
            size_t off0 = (size_t)mrow0*Ntot + n;
            size_t off1 = (size_t)mrow1*Ntot + n;
            if (RES){
                float2 r0 = *(const float2*)(res + off0);
                float2 r1 = *(const float2*)(res + off1);
                v00+=r0.x; v01+=r0.y; v10+=r1.x; v11+=r1.y;
            }
            if (W32){
                *(float2*)(C32 + off0) = make_float2(v00,v01);
                *(float2*)(C32 + off1) = make_float2(v10,v11);
            }
            if (W16){
                *(__half2*)(C16 + off0) = __floats2half2_rn(v00,v01);
                *(__half2*)(C16 + off1) = __floats2half2_rn(v10,v11);
            }
        }
    }
}

// ---------------- Flash attention: block per (q-tile64, head, batch) ----------
__global__ void __launch_bounds__(256) attn_kernel(
    const float* __restrict__ QKV, __half* __restrict__ Z)
{
    __shared__ __align__(16) float Qs[64][64];   // [q][d], pre-scaled
    __shared__ __align__(16) float KT[64][64];   // [d][k]  (reused as P[q][k])
    __shared__ __align__(16) float Vs[64][64];   // [k][e]

    int qt = gridDim.x - 1 - blockIdx.x;  // longest blocks launch first
    int h  = blockIdx.y;
    int b  = blockIdx.z;
    int q0 = qt*64;
    int tid = threadIdx.x, tx = tid & 15, ty = tid >> 4;

    const float* base = QKV + (size_t)b*SEQ*QKVLD + h*DH;

    #pragma unroll
    for (int i=0;i<4;i++){
        int idx = tid + i*256;
        int r = idx >> 4, c4 = (idx & 15)*4;
        float4 v = *(const float4*)(base + (size_t)(q0+r)*QKVLD + c4);
        v.x*=0.125f; v.y*=0.125f; v.z*=0.125f; v.w*=0.125f;
        *(float4*)&Qs[r][c4] = v;
    }

    float m[4], l[4], acc[4][4];
    #pragma unroll
    for (int i=0;i<4;i++){
        m[i]=-INFINITY; l[i]=0.f;
        #pragma unroll
        for (int j=0;j<4;j++) acc[i][j]=0.f;
    }

    int nkt = qt + 1;
    for (int kt=0; kt<nkt; kt++){
        int k0 = kt*64;
        __syncthreads();
        #pragma unroll
        for (int i=0;i<4;i++){
            int idx = tid + i*256;
            int r = idx >> 4, c4 = (idx & 15)*4;
            float4 kv = *(const float4*)(base + 768  + (size_t)(k0+r)*QKVLD + c4);
            KT[c4+0][r]=kv.x; KT[c4+1][r]=kv.y; KT[c4+2][r]=kv.z; KT[c4+3][r]=kv.w;
            float4 vv = *(const float4*)(base + 1536 + (size_t)(k0+r)*QKVLD + c4);
            *(float4*)&Vs[r][c4] = vv;
        }
        __syncthreads();

        float s[4][4];
        #pragma unroll
        for (int i=0;i<4;i++)
            #pragma unroll
            for (int j=0;j<4;j++) s[i][j]=0.f;

        #pragma unroll
        for (int d=0; d<64; d+=4){
            float4 q4[4], k4[4];
            #pragma unroll
            for (int ii=0;ii<4;ii++) q4[ii] = *(const float4*)&Qs[ty*4+ii][d];
            #pragma unroll
            for (int c2=0;c2<4;c2++) k4[c2] = *(const float4*)&KT[d+c2][tx*4];
            #pragma unroll
            for (int ii=0;ii<4;ii++){
                float qa[4] = {q4[ii].x, q4[ii].y, q4[ii].z, q4[ii].w};
                #pragma unroll
                for (int c2=0;c2<4;c2++){
                    s[ii][0] = fmaf(qa[c2], k4[c2].x, s[ii][0]);
                    s[ii][1] = fmaf(qa[c2], k4[c2].y, s[ii][1]);
                    s[ii][2] = fmaf(qa[c2], k4[c2].z, s[ii][2]);
                    s[ii][3] = fmaf(qa[c2], k4[c2].w, s[ii][3]);
                }
            }
        }

        if (kt == qt){
            #pragma unroll
            for (int ii=0;ii<4;ii++)
                #pragma unroll
                for (int jj=0;jj<4;jj++)
                    if (k0 + tx*4 + jj > q0 + ty*4 + ii) s[ii][jj] = -INFINITY;
        }

        #pragma unroll
        for (int ii=0;ii<4;ii++){
            float tm = fmaxf(fmaxf(s[ii][0],s[ii][1]), fmaxf(s[ii][2],s[ii][3]));
            #pragma unroll
            for (int o=8;o>0;o>>=1) tm = fmaxf(tm, __shfl_xor_sync(~0u, tm, o));
            float nm = fmaxf(m[ii], tm);
            float alpha = __expf(m[ii]-nm);
            float psum = 0.f;
            #pragma unroll
            for (int jj=0;jj<4;jj++){
                float p = __expf(s[ii][jj]-nm);
                s[ii][jj] = p; psum += p;
            }
            #pragma unroll
            for (int o=8;o>0;o>>=1) psum += __shfl_xor_sync(~0u, psum, o);
            l[ii] = l[ii]*alpha + psum;
            m[ii] = nm;
            #pragma unroll
            for (int jj=0;jj<4;jj++) acc[ii][jj]*=alpha;
        }

        __syncthreads();
        #pragma unroll
        for (int ii=0;ii<4;ii++)
            *(float4*)&KT[ty*4+ii][tx*4] = make_float4(s[ii][0],s[ii][1],s[ii][2],s[ii][3]);
        __syncthreads();

        #pragma unroll
        for (int k=0;k<64;k+=4){
            float4 p4[4], v4[4];
            #pragma unroll
            for (int ii=0;ii<4;ii++) p4[ii] = *(const float4*)&KT[ty*4+ii][k];
            #pragma unroll
            for (int c2=0;c2<4;c2++) v4[c2] = *(const float4*)&Vs[k+c2][tx*4];
            #pragma unroll
            for (int ii=0;ii<4;ii++){
                float pa[4] = {p4[ii].x, p4[ii].y, p4[ii].z, p4[ii].w};
                #pragma unroll
                for (int c2=0;c2<4;c2++){
                    acc[ii][0] = fmaf(pa[c2], v4[c2].x, acc[ii][0]);
                    acc[ii][1] = fmaf(pa[c2], v4[c2].y, acc[ii][1]);
                    acc[ii][2] = fmaf(pa[c2], v4[c2].z, acc[ii][2]);
                    acc[ii][3] = fmaf(pa[c2], v4[c2].w, acc[ii][3]);
                }
            }
        }
    }

    __half* outp = Z + ((size_t)b*SEQ + q0)*DMODEL + h*DH;
    #pragma unroll
    for (int ii=0;ii<4;ii++){
        float inv = 1.0f/l[ii];
        __half2* p = (__half2*)&outp[(size_t)(ty*4+ii)*DMODEL + tx*4];
        p[0] = __floats2half2_rn(acc[ii][0]*inv, acc[ii][1]*inv);
        p[1] = __floats2half2_rn(acc[ii][2]*inv, acc[ii][3]*inv);
    }
}

// ---------------- launch ----------------
extern "C" void kernel_launch(void* const* d_in, const int* in_sizes, int n_in,
                              void* d_out, int out_size)
{
    const float* resid = (const float*)d_in[0];
    const float* WQ    = (const float*)d_in[1];
    const float* WK    = (const float*)d_in[2];
    const float* WV    = (const float*)d_in[3];
    const float* WO    = (const float*)d_in[4];   // [12,64,768] == [768,768] row-major
    const float* bQ    = (const float*)d_in[5];
    const float* bK    = (const float*)d_in[6];
    const float* bV    = (const float*)d_in[7];
    const float* bO    = (const float*)d_in[8];
    const float* ln1w  = (const float*)d_in[9];
    const float* ln1b  = (const float*)d_in[10];
    const float* ln2w  = (const float*)d_in[11];
    const float* ln2b  = (const float*)d_in[12];
    const float* Win   = (const float*)d_in[13];
    const float* bin   = (const float*)d_in[14];
    const float* Wout  = (const float*)d_in[15];
    const float* bout  = (const float*)d_in[16];
    float* out = (float*)d_out;

    __half *x1h, *x2h, *zh, *hh, *wqkvh, *woh, *winh, *wouth;
    float *bqkv, *qkv, *mid;
    cudaGetSymbolAddress((void**)&x1h,   g_x1h);
    cudaGetSymbolAddress((void**)&x2h,   g_x2h);
    cudaGetSymbolAddress((void**)&zh,    g_zh);
    cudaGetSymbolAddress((void**)&hh,    g_hh);
    cudaGetSymbolAddress((void**)&wqkvh, g_wqkvh);
    cudaGetSymbolAddress((void**)&woh,   g_woh);
    cudaGetSymbolAddress((void**)&winh,  g_winh);
    cudaGetSymbolAddress((void**)&wouth, g_wouth);
    cudaGetSymbolAddress((void**)&bqkv,  g_bqkv);
    cudaGetSymbolAddress((void**)&qkv,   g_qkv);
    cudaGetSymbolAddress((void**)&mid,   g_mid);

    repack_qkv_kernel<<<(QKVLD*DMODEL + 255)/256, 256>>>(WQ, WK, WV, bQ, bK, bV);
    repack_t_kernel<<<(DMODEL*DMODEL + 255)/256, 256>>>(WO,   woh,   DMODEL, DMODEL);
    repack_t_kernel<<<(DMLP*DMODEL   + 255)/256, 256>>>(Win,  winh,  DMLP,   DMODEL);
    repack_t_kernel<<<(DMODEL*DMLP   + 255)/256, 256>>>(Wout, wouth, DMODEL, DMLP);

    ln_kernel<<<TOKENS, 256>>>(resid, ln1w, ln1b, x1h);
    hgemm<false,false,true,false><<<dim3(QKVLD/128, TOKENS/128), 256>>>(
        x1h, wqkvh, bqkv, nullptr, qkv, nullptr, QKVLD, DMODEL);
    attn_kernel<<<dim3(SEQ/64, NH, BATCH), 256>>>(qkv, zh);
    hgemm<false,true,true,false><<<dim3(DMODEL/128, TOKENS/128), 256>>>(
        zh, woh, bO, resid, mid, nullptr, DMODEL, DMODEL);
    ln_kernel<<<TOKENS, 256>>>(mid, ln2w, ln2b, x2h);
    hgemm<true,false,false,true><<<dim3(DMLP/128, TOKENS/128), 256>>>(
        x2h, winh, bin, nullptr, nullptr, hh, DMLP, DMODEL);
    hgemm<false,true,true,false><<<dim3(DMODEL/128, TOKENS/128), 256>>>(
        hh, wouth, bout, mid, out, nullptr, DMODEL, DMLP);
}

// round 17
// speedup vs baseline: 4.0334x; 1.6041x over previous
#include <cuda_runtime.h>
#include <cuda_fp16.h>
#include <math.h>

#define TOKENS 8192
#define DMODEL 768
#define DMLP   3072
#define NH     12
#define DH     64
#define SEQ    1024
#define BATCH  8
#define QKVLD  2304
#define SA     40   // GEMM smem row stride in halves (80B): conflict-free for ldmatrix
#define SB     72   // attn smem row stride in halves (144B): conflict-free, >=64 cols

// ---------------- scratch (device globals: no allocs allowed) ----------------
__device__ __half g_x1h [TOKENS*DMODEL];
__device__ __half g_x2h [TOKENS*DMODEL];
__device__ __half g_zh  [TOKENS*DMODEL];
__device__ __half g_hh  [TOKENS*DMLP];
__device__ __half g_qkvh[TOKENS*QKVLD];
__device__ __half g_wqkvh[QKVLD*DMODEL];   // [N=2304][K=768]
__device__ __half g_woh  [DMODEL*DMODEL];  // [N=768][K=768]
__device__ __half g_winh [DMLP*DMODEL];    // [N=3072][K=768]
__device__ __half g_wouth[DMODEL*DMLP];    // [N=768][K=3072]
__device__ float  g_bqkv[QKVLD];
__device__ float  g_mid [TOKENS*DMODEL];

// ---------------- small helpers ----------------
__device__ __forceinline__ float fast_tanh(float x){
    float r; asm("tanh.approx.f32 %0, %1;" : "=f"(r) : "f"(x)); return r;
}
__device__ __forceinline__ float gelu_fn(float x){
    float u = x + 0.044715f*x*x*x;
    return 0.5f*x*(1.0f + fast_tanh(0.7978845608028654f*u));
}
__device__ __forceinline__ unsigned smem_u32(const void* p){
    unsigned a;
    asm("{ .reg .u64 t; cvta.to.shared.u64 t, %1; cvt.u32.u64 %0, t; }" : "=r"(a) : "l"(p));
    return a;
}
__device__ __forceinline__ float fast_ex2(float x){
    float r; asm("ex2.approx.f32 %0, %1;" : "=f"(r) : "f"(x)); return r;
}
__device__ __forceinline__ unsigned h2ex2(unsigned x){
    unsigned r; asm("ex2.approx.f16x2 %0, %1;" : "=r"(r) : "r"(x)); return r;
}

#define LDSM4(r0,r1,r2,r3, addr) \
    asm volatile("ldmatrix.sync.aligned.m8n8.x4.shared.b16 {%0,%1,%2,%3}, [%4];" \
        : "=r"(r0),"=r"(r1),"=r"(r2),"=r"(r3) : "r"(addr))

#define LDSM4T(r0,r1,r2,r3, addr) \
    asm volatile("ldmatrix.sync.aligned.m8n8.x4.trans.shared.b16 {%0,%1,%2,%3}, [%4];" \
        : "=r"(r0),"=r"(r1),"=r"(r2),"=r"(r3) : "r"(addr))

#define MMA16816(c0,c1,c2,c3, a0,a1,a2,a3, b0,b1) \
    asm volatile("mma.sync.aligned.m16n8k16.row.col.f32.f16.f16.f32 " \
        "{%0,%1,%2,%3}, {%4,%5,%6,%7}, {%8,%9}, {%0,%1,%2,%3};" \
        : "+f"(c0),"+f"(c1),"+f"(c2),"+f"(c3) \
        : "r"(a0),"r"(a1),"r"(a2),"r"(a3), "r"(b0),"r"(b1))

// ---------------- weight repack kernels (fp32 -> fp16, transposed to [N][K]) --
__global__ void __launch_bounds__(256) repack_qkv_kernel(
    const float* __restrict__ WQ, const float* __restrict__ WK, const float* __restrict__ WV,
    const float* __restrict__ bQ, const float* __restrict__ bK, const float* __restrict__ bV)
{
    int idx = blockIdx.x*256 + threadIdx.x;
    if (idx < QKVLD*DMODEL) {
        int n = idx / DMODEL;
        int k = idx % DMODEL;
        int which = n / DMODEL;
        int r = n % DMODEL;
        int h = r >> 6, e = r & 63;
        const float* W = (which==0) ? WQ : (which==1) ? WK : WV;
        g_wqkvh[idx] = __float2half(W[(h*DMODEL + k)*DH + e]);
    }
    if (idx < QKVLD) {
        int which = idx / DMODEL, r = idx % DMODEL;
        const float* bb = (which==0) ? bQ : (which==1) ? bK : bV;
        g_bqkv[idx] = bb[r];
    }
}

__global__ void __launch_bounds__(256) repack_t_kernel(
    const float* __restrict__ W, __half* __restrict__ out, int N, int K)
{
    int idx = blockIdx.x*256 + threadIdx.x;
    if (idx < N*K) {
        int n = idx / K, k = idx % K;
        out[idx] = __float2half(W[(size_t)k*N + n]);
    }
}

// ---------------- LayerNorm: one block per token, fp16 out ----------------
__global__ void __launch_bounds__(256) ln_kernel(
    const float* __restrict__ x, const float* __restrict__ w,
    const float* __restrict__ b, __half* __restrict__ y)
{
    int t = blockIdx.x;
    const float* xr = x + (size_t)t*DMODEL;
    __half*      yr = y + (size_t)t*DMODEL;
    int tid = threadIdx.x;
    float v0 = xr[tid], v1 = xr[tid+256], v2 = xr[tid+512];
    float s  = v0+v1+v2;
    float s2 = v0*v0 + v1*v1 + v2*v2;
    #pragma unroll
    for (int o=16;o>0;o>>=1){ s += __shfl_xor_sync(~0u,s,o); s2 += __shfl_xor_sync(~0u,s2,o); }
    __shared__ float sh[16];
    int warp = tid>>5, lane = tid&31;
    if (lane==0){ sh[warp]=s; sh[8+warp]=s2; }
    __syncthreads();
    if (tid==0){
        float a=0.f,c=0.f;
        #pragma unroll
        for (int i=0;i<8;i++){ a+=sh[i]; c+=sh[8+i]; }
        float mean = a*(1.0f/DMODEL);
        float var  = c*(1.0f/DMODEL) - mean*mean;
        sh[0]=mean; sh[1]=rsqrtf(var+1e-5f);
    }
    __syncthreads();
    float mean=sh[0], rstd=sh[1];
    yr[tid]     = __float2half((v0-mean)*rstd*w[tid]     + b[tid]);
    yr[tid+256] = __float2half((v1-mean)*rstd*w[tid+256] + b[tid+256]);
    yr[tid+512] = __float2half((v2-mean)*rstd*w[tid+512] + b[tid+512]);
}

// ---------------- HMMA fp16 GEMM (unchanged from R12 win) ---------------------
__device__ __forceinline__ void compute_tile(unsigned Abase, unsigned Bbase,
                                             float c[4][4][4])
{
    #pragma unroll
    for (int kk=0; kk<2; kk++){
        unsigned a[4][4], b[2][4];
        #pragma unroll
        for (int mi=0; mi<4; mi++)
            LDSM4(a[mi][0],a[mi][1],a[mi][2],a[mi][3],
                  Abase + (unsigned)((mi*16*SA + kk*16)*2));
        #pragma unroll
        for (int ni=0; ni<2; ni++)
            LDSM4(b[ni][0],b[ni][1],b[ni][2],b[ni][3],
                  Bbase + (unsigned)((ni*16*SA + kk*16)*2));
        #pragma unroll
        for (int mi=0; mi<4; mi++)
            #pragma unroll
            for (int j=0; j<4; j++){
                int ni = j>>1, s = j&1;
                MMA16816(c[mi][j][0],c[mi][j][1],c[mi][j][2],c[mi][j][3],
                         a[mi][0],a[mi][1],a[mi][2],a[mi][3],
                         b[ni][s], b[ni][s+2]);
            }
    }
}

template<bool GELU, bool RES, bool W32, bool W16>
__global__ void __launch_bounds__(256,2) hgemm(
    const __half* __restrict__ A, const __half* __restrict__ Bw,
    const float* __restrict__ bias, const float* __restrict__ res,
    float* __restrict__ C32, __half* __restrict__ C16, int Ntot, int K)
{
    __shared__ __align__(16) __half As[2][128*SA];
    __shared__ __align__(16) __half Bs[2][128*SA];

    int tid = threadIdx.x, lane = tid&31, wid = tid>>5;
    int wm = wid>>2, wn = wid&3;
    int m0 = blockIdx.y*128, n0 = blockIdx.x*128;

    int lr = tid>>1;
    int lc = (tid&1)*16;
    const __half* Ap = A  + (size_t)(m0+lr)*K + lc;
    const __half* Bp = Bw + (size_t)(n0+lr)*K + lc;
    int soff = lr*SA + lc;

    float c[4][4][4];
    #pragma unroll
    for (int i=0;i<4;i++)
        #pragma unroll
        for (int j=0;j<4;j++)
            #pragma unroll
            for (int k=0;k<4;k++) c[i][j][k]=0.f;

    unsigned a_lane = (unsigned)(((wm*64 + (lane&15))*SA + (lane>>4)*8)*2);
    unsigned b_lane = (unsigned)(((wn*32 + (lane&15))*SA + (lane>>4)*8)*2);
    unsigned As0 = smem_u32(&As[0][0]), As1 = smem_u32(&As[1][0]);
    unsigned Bs0 = smem_u32(&Bs[0][0]), Bs1 = smem_u32(&Bs[1][0]);

    {
        uint4 a0 = *(const uint4*)(Ap);
        uint4 a1 = *(const uint4*)(Ap+8);
        uint4 b0 = *(const uint4*)(Bp);
        uint4 b1 = *(const uint4*)(Bp+8);
        *(uint4*)&As[0][soff]   = a0; *(uint4*)&As[0][soff+8] = a1;
        *(uint4*)&Bs[0][soff]   = b0; *(uint4*)&Bs[0][soff+8] = b1;
    }
    __syncthreads();

    int nks = K >> 5;
    int buf = 0;
    for (int ks=1; ks<nks; ks++){
        const __half* Ap2 = Ap + ks*32;
        const __half* Bp2 = Bp + ks*32;
        uint4 a0 = *(const uint4*)(Ap2);
        uint4 a1 = *(const uint4*)(Ap2+8);
        uint4 b0 = *(const uint4*)(Bp2);
        uint4 b1 = *(const uint4*)(Bp2+8);

        compute_tile((buf?As1:As0)+a_lane, (buf?Bs1:Bs0)+b_lane, c);

        int nb = buf^1;
        __half* Asw = nb ? &As[1][0] : &As[0][0];
        __half* Bsw = nb ? &Bs[1][0] : &Bs[0][0];
        *(uint4*)&Asw[soff]   = a0; *(uint4*)&Asw[soff+8] = a1;
        *(uint4*)&Bsw[soff]   = b0; *(uint4*)&Bsw[soff+8] = b1;
        __syncthreads();
        buf = nb;
    }
    compute_tile((buf?As1:As0)+a_lane, (buf?Bs1:Bs0)+b_lane, c);

    int rr = lane>>2, cc = (lane&3)*2;
    #pragma unroll
    for (int mi=0; mi<4; mi++){
        int mrow0 = m0 + wm*64 + mi*16 + rr;
        int mrow1 = mrow0 + 8;
        #pragma unroll
        for (int j=0; j<4; j++){
            int n = n0 + wn*32 + j*8 + cc;
            float2 b2 = *(const float2*)(bias + n);
            float v00 = c[mi][j][0] + b2.x, v01 = c[mi][j][1] + b2.y;
            float v10 = c[mi][j][2] + b2.x, v11 = c[mi][j][3] + b2.y;
            if (GELU){
                v00=gelu_fn(v00); v01=gelu_fn(v01);
                v10=gelu_fn(v10); v11=gelu_fn(v11);
            }
            size_t off0 = (size_t)mrow0*Ntot + n;
            size_t off1 = (size_t)mrow1*Ntot + n;
            if (RES){
                float2 r0 = *(const float2*)(res + off0);
                float2 r1 = *(const float2*)(res + off1);
                v00+=r0.x; v01+=r0.y; v10+=r1.x; v11+=r1.y;
            }
            if (W32){
                *(float2*)(C32 + off0) = make_float2(v00,v01);
                *(float2*)(C32 + off1) = make_float2(v10,v11);
            }
            if (W16){
                *(__half2*)(C16 + off0) = __floats2half2_rn(v00,v01);
                *(__half2*)(C16 + off1) = __floats2half2_rn(v10,v11);
            }
        }
    }
}

// ---------------- HMMA flash attention ----------------------------------------
// block = 128 threads (4 warps), q-tile 64 (16 rows/warp), fp16 QKV, f16x2 exp2.
__global__ void __launch_bounds__(128) attn_kernel(
    const __half* __restrict__ QKV, __half* __restrict__ Z)
{
    __shared__ __align__(16) __half Qs[64*SB];
    __shared__ __align__(16) __half Ks[64*SB];
    __shared__ __align__(16) __half Vs[64*SB];

    int qt = gridDim.x - 1 - blockIdx.x;
    int h  = blockIdx.y;
    int b  = blockIdx.z;
    int q0 = qt*64;
    int tid = threadIdx.x, lane = tid&31, warp = tid>>5;

    const __half* base = QKV + (size_t)b*SEQ*QKVLD + h*DH;
    const float SCALE2 = 0.125f * 1.4426950408889634f;   // 1/sqrt(64) * log2(e)

    // load Q tile [64][64] -> smem stride SB
    #pragma unroll
    for (int i=0;i<4;i++){
        int t = tid + i*128;            // 0..511
        int r = t>>3, c8 = (t&7)*8;
        *(uint4*)&Qs[r*SB + c8] = *(const uint4*)(base + (size_t)(q0+r)*QKVLD + c8);
    }

    unsigned qs = smem_u32(Qs), ks = smem_u32(Ks), vs = smem_u32(Vs);
    unsigned a_q = qs + ((warp*16 + (lane&15))*SB + (lane>>4)*8)*2;

    float m0v=-INFINITY, m1v=-INFINITY, l0=0.f, l1=0.f;
    float o[8][4];
    #pragma unroll
    for (int j=0;j<8;j++)
        #pragma unroll
        for (int i=0;i<4;i++) o[j][i]=0.f;

    int rr = lane>>2, cc = (lane&3)*2;
    int nkt = qt + 1;

    for (int kt=0; kt<nkt; kt++){
        int k0 = kt*64;
        __syncthreads();
        #pragma unroll
        for (int i=0;i<4;i++){
            int t = tid + i*128;
            int r = t>>3, c8 = (t&7)*8;
            *(uint4*)&Ks[r*SB + c8] = *(const uint4*)(base + 768  + (size_t)(k0+r)*QKVLD + c8);
            *(uint4*)&Vs[r*SB + c8] = *(const uint4*)(base + 1536 + (size_t)(k0+r)*QKVLD + c8);
        }
        __syncthreads();

        // S = Q K^T : c[8][4] covers 16 q-rows x 64 kv
        float c[8][4];
        #pragma unroll
        for (int j=0;j<8;j++)
            #pragma unroll
            for (int i=0;i<4;i++) c[j][i]=0.f;

        #pragma unroll
        for (int kk=0; kk<4; kk++){
            unsigned a0,a1,a2,a3;
            LDSM4(a0,a1,a2,a3, a_q + kk*32);
            #pragma unroll
            for (int nb=0; nb<4; nb++){
                unsigned b0,b1,b2,b3;
                LDSM4(b0,b1,b2,b3, ks + ((nb*16 + (lane&15))*SB + kk*16 + (lane>>4)*8)*2);
                MMA16816(c[nb*2][0],c[nb*2][1],c[nb*2][2],c[nb*2][3],
                         a0,a1,a2,a3, b0,b2);
                MMA16816(c[nb*2+1][0],c[nb*2+1][1],c[nb*2+1][2],c[nb*2+1][3],
                         a0,a1,a2,a3, b1,b3);
            }
        }

        // scale to base-2 domain
        #pragma unroll
        for (int j=0;j<8;j++)
            #pragma unroll
            for (int i=0;i<4;i++) c[j][i] *= SCALE2;

        if (kt == qt){   // causal mask on diagonal tile
            int row0 = q0 + warp*16 + rr;
            #pragma unroll
            for (int j=0;j<8;j++){
                int col = k0 + j*8 + cc;
                if (col   > row0  ) c[j][0] = -INFINITY;
                if (col+1 > row0  ) c[j][1] = -INFINITY;
                if (col   > row0+8) c[j][2] = -INFINITY;
                if (col+1 > row0+8) c[j][3] = -INFINITY;
            }
        }

        // row maxima (per lane over its 16 cols, then across quad)
        float tm0 = -INFINITY, tm1 = -INFINITY;
        #pragma unroll
        for (int j=0;j<8;j++){
            tm0 = fmaxf(tm0, fmaxf(c[j][0], c[j][1]));
            tm1 = fmaxf(tm1, fmaxf(c[j][2], c[j][3]));
        }
        #pragma unroll
        for (int o2=1; o2<4; o2<<=1){
            tm0 = fmaxf(tm0, __shfl_xor_sync(~0u, tm0, o2));
            tm1 = fmaxf(tm1, __shfl_xor_sync(~0u, tm1, o2));
        }
        float nm0 = fmaxf(m0v, tm0), nm1 = fmaxf(m1v, tm1);
        float al0 = fast_ex2(m0v - nm0), al1 = fast_ex2(m1v - nm1);
        m0v = nm0; m1v = nm1;

        // p = exp2(c - nm) via f16x2 MUFU; accumulate row sums in fp32
        unsigned ph[8][2];
        float ps0 = 0.f, ps1 = 0.f;
        #pragma unroll
        for (int j=0;j<8;j++){
            __half2 e01 = __floats2half2_rn(c[j][0]-nm0, c[j][1]-nm0);
            __half2 e23 = __floats2half2_rn(c[j][2]-nm1, c[j][3]-nm1);
            ph[j][0] = h2ex2(*(unsigned*)&e01);
            ph[j][1] = h2ex2(*(unsigned*)&e23);
            float2 f01 = __half22float2(*(__half2*)&ph[j][0]);
            float2 f23 = __half22float2(*(__half2*)&ph[j][1]);
            ps0 += f01.x + f01.y;
            ps1 += f23.x + f23.y;
        }
        #pragma unroll
        for (int o2=1; o2<4; o2<<=1){
            ps0 += __shfl_xor_sync(~0u, ps0, o2);
            ps1 += __shfl_xor_sync(~0u, ps1, o2);
        }
        l0 = l0*al0 + ps0;
        l1 = l1*al1 + ps1;

        // rescale O accumulators
        #pragma unroll
        for (int j=0;j<8;j++){
            o[j][0]*=al0; o[j][1]*=al0; o[j][2]*=al1; o[j][3]*=al1;
        }

        // O += P V  (P regs as A-frag; V via ldmatrix.trans as B-frag)
        #pragma unroll
        for (int kk=0; kk<4; kk++){
            unsigned a0 = ph[2*kk][0], a1 = ph[2*kk][1];
            unsigned a2 = ph[2*kk+1][0], a3 = ph[2*kk+1][1];
            #pragma unroll
            for (int db=0; db<4; db++){
                unsigned v0,v1,v2,v3;
                LDSM4T(v0,v1,v2,v3, vs + ((kk*16 + (lane&15))*SB + db*16 + (lane>>4)*8)*2);
                MMA16816(o[db*2][0],o[db*2][1],o[db*2][2],o[db*2][3],
                         a0,a1,a2,a3, v0,v1);
                MMA16816(o[db*2+1][0],o[db*2+1][1],o[db*2+1][2],o[db*2+1][3],
                         a0,a1,a2,a3, v2,v3);
            }
        }
    }

    float inv0 = 1.0f/l0, inv1 = 1.0f/l1;
    int row0 = q0 + warp*16 + rr;
    __half* zp = Z + ((size_t)b*SEQ)*DMODEL + h*DH;
    #pragma unroll
    for (int j=0;j<8;j++){
        int d = j*8 + cc;
        *(__half2*)&zp[(size_t)(row0  )*DMODEL + d] = __floats2half2_rn(o[j][0]*inv0, o[j][1]*inv0);
        *(__half2*)&zp[(size_t)(row0+8)*DMODEL + d] = __floats2half2_rn(o[j][2]*inv1, o[j][3]*inv1);
    }
}

// ---------------- launch ----------------
extern "C" void kernel_launch(void* const* d_in, const int* in_sizes, int n_in,
                              void* d_out, int out_size)
{
    const float* resid = (const float*)d_in[0];
    const float* WQ    = (const float*)d_in[1];
    const float* WK    = (const float*)d_in[2];
    const float* WV    = (const float*)d_in[3];
    const float* WO    = (const float*)d_in[4];
    const float* bQ    = (const float*)d_in[5];
    const float* bK    = (const float*)d_in[6];
    const float* bV    = (const float*)d_in[7];
    const float* bO    = (const float*)d_in[8];
    const float* ln1w  = (const float*)d_in[9];
    const float* ln1b  = (const float*)d_in[10];
    const float* ln2w  = (const float*)d_in[11];
    const float* ln2b  = (const float*)d_in[12];
    const float* Win   = (const float*)d_in[13];
    const float* bin   = (const float*)d_in[14];
    const float* Wout  = (const float*)d_in[15];
    const float* bout  = (const float*)d_in[16];
    float* out = (float*)d_out;

    __half *x1h, *x2h, *zh, *hh, *qkvh, *wqkvh, *woh, *winh, *wouth;
    float *bqkv, *mid;
    cudaGetSymbolAddress((void**)&x1h,   g_x1h);
    cudaGetSymbolAddress((void**)&x2h,   g_x2h);
    cudaGetSymbolAddress((void**)&zh,    g_zh);
    cudaGetSymbolAddress((void**)&hh,    g_hh);
    cudaGetSymbolAddress((void**)&qkvh,  g_qkvh);
    cudaGetSymbolAddress((void**)&wqkvh, g_wqkvh);
    cudaGetSymbolAddress((void**)&woh,   g_woh);
    cudaGetSymbolAddress((void**)&winh,  g_winh);
    cudaGetSymbolAddress((void**)&wouth, g_wouth);
    cudaGetSymbolAddress((void**)&bqkv,  g_bqkv);
    cudaGetSymbolAddress((void**)&mid,   g_mid);

    repack_qkv_kernel<<<(QKVLD*DMODEL + 255)/256, 256>>>(WQ, WK, WV, bQ, bK, bV);
    repack_t_kernel<<<(DMODEL*DMODEL + 255)/256, 256>>>(WO,   woh,   DMODEL, DMODEL);
    repack_t_kernel<<<(DMLP*DMODEL   + 255)/256, 256>>>(Win,  winh,  DMLP,   DMODEL);
    repack_t_kernel<<<(DMODEL*DMLP   + 255)/256, 256>>>(Wout, wouth, DMODEL, DMLP);

    ln_kernel<<<TOKENS, 256>>>(resid, ln1w, ln1b, x1h);
    hgemm<false,false,false,true><<<dim3(QKVLD/128, TOKENS/128), 256>>>(
        x1h, wqkvh, bqkv, nullptr, nullptr, qkvh, QKVLD, DMODEL);
    attn_kernel<<<dim3(SEQ/64, NH, BATCH), 128>>>(qkvh, zh);
    hgemm<false,true,true,false><<<dim3(DMODEL/128, TOKENS/128), 256>>>(
        zh, woh, bO, resid, mid, nullptr, DMODEL, DMODEL);
    ln_kernel<<<TOKENS, 256>>>(mid, ln2w, ln2b, x2h);
    hgemm<true,false,false,true><<<dim3(DMLP/128, TOKENS/128), 256>>>(
        x2h, winh, bin, nullptr, nullptr, hh, DMLP, DMODEL);
    hgemm<false,true,true,false><<<dim3(DMODEL/128, TOKENS/128), 256>>>(
        hh, wouth, bout, mid, out, nullptr, DMODEL, DMLP);
}